// round 7
// baseline (speedup 1.0000x reference)
#include <cuda_runtime.h>
#include <cstdint>
#include <cstddef>

// ---------------- problem constants ----------------
#define Bn   4
#define Cc   128
#define Hh   128
#define Wd   256
#define HW   (Hh*Wd)          // 32768
#define Ff   128
#define CVC  49
#define RAD  24
#define NPIX (Bn*HW)          // 131072
static const size_t NC_ = (size_t)Bn * CVC * HW;  // elements per corr-like tensor

// ---------------- device scratch (static, no allocation) ----------------
__device__ float g_f1n[(size_t)NPIX * Ff];   // [B][F][H][W]
__device__ float g_f2n[(size_t)NPIX * Ff];
__device__ float g_Wt1[Cc * Ff];             // W transposed: [c][o]
__device__ float g_Wt2[Cc * Ff];
__device__ float g_M[9 * CVC];               // [i][j][c], i=volume, j=logit
__device__ float g_beta[3];

// ---------------- helpers ----------------
__device__ __forceinline__ unsigned long long bcast2(float v) {
    unsigned long long r; asm("mov.b64 %0, {%1,%1};" : "=l"(r) : "f"(v)); return r;
}
__device__ __forceinline__ void unpack2(unsigned long long p, float& lo, float& hi) {
    asm("mov.b64 {%0,%1}, %2;" : "=f"(lo), "=f"(hi) : "l"(p));
}
__device__ __forceinline__ void ffma2(unsigned long long& acc, unsigned long long a, unsigned long long b) {
    asm("fma.rn.f32x2 %0, %1, %2, %0;" : "+l"(acc) : "l"(a), "l"(b));
}
__device__ __forceinline__ void cp16(void* smem_dst, const void* gmem_src) {
    unsigned int s = (unsigned int)__cvta_generic_to_shared(smem_dst);
    asm volatile("cp.async.cg.shared.global [%0], [%1], 16;" :: "r"(s), "l"(gmem_src));
}
__device__ __forceinline__ void cp_commit() { asm volatile("cp.async.commit_group;"); }
template <int N>
__device__ __forceinline__ void cp_wait() { asm volatile("cp.async.wait_group %0;" :: "n"(N)); }

// ---------------- prep: tiled transpose + selector fold ----------------
// blocks 0..15: 32x32 transpose tiles for Wt1/Wt2; 16..18: M per volume; 19: beta.
__global__ void prep_kernel(const float* __restrict__ Wf1, const float* __restrict__ Wf2,
                            const float* __restrict__ Wgeo, const float* __restrict__ bgeo,
                            const float* __restrict__ Wsel, const float* __restrict__ bsel)
{
    __shared__ float t1[32][33], t2[32][33];
    int blk = blockIdx.x, t = threadIdx.x;
    if (blk < 16) {
        int oT = (blk >> 2) * 32;          // o tile base
        int cT = (blk & 3) * 32;           // c tile base
        #pragma unroll
        for (int i = 0; i < 4; i++) {
            int idx = t + i * 256;
            int r = idx >> 5, cl = idx & 31;
            t1[r][cl] = Wf1[(oT + r) * Cc + cT + cl];
            t2[r][cl] = Wf2[(oT + r) * Cc + cT + cl];
        }
        __syncthreads();
        #pragma unroll
        for (int i = 0; i < 4; i++) {
            int idx = t + i * 256;
            int r = idx >> 5, cl = idx & 31;
            g_Wt1[(cT + r) * Ff + oT + cl] = t1[cl][r];
            g_Wt2[(cT + r) * Ff + oT + cl] = t2[cl][r];
        }
    } else if (blk < 19) {
        int i = blk - 16;                            // volume index
        for (int r = t; r < 3 * CVC; r += 256) {     // j*CVC + c
            int j = r / CVC, c = r % CVC;
            float s = 0.f;
            #pragma unroll 8
            for (int m = 0; m < 96; m++)
                s += Wsel[j * 288 + i * 96 + m] * Wgeo[m * CVC + c];
            g_M[i * 3 * CVC + j * CVC + c] = s;
        }
    } else {
        if (t < 3) {
            float s = bsel[t];
            for (int q = 0; q < 288; q++)
                s += Wsel[t * 288 + q] * bgeo[q % 96];
            g_beta[t] = s;
        }
    }
}

// ---------------- fmap: conv1x1 GEMM + L2-normalize ----------------
// tile: 256 px (one full image row) x 128 outputs, K-tiles of 32, cp.async 2-stage.
// thread micro-tile: 8 outputs x 16 px (4 chunks of 4 px at stride 64).
// 1 CTA/SM (regs ~180); smem traffic 0.5 B/MAC -> FFMA2-bound.
#define FMK 32
#define FROW 264          // feat smem row stride (256 + 8 pad)

extern __shared__ float dynsm[];

__global__ __launch_bounds__(256) void fmap_kernel(
    const float* __restrict__ featA, const float* __restrict__ featB,
    const float* __restrict__ biasA, const float* __restrict__ biasB)
{
    float* fS0 = dynsm;                       // 32 x 264
    float* fS1 = fS0 + FMK * FROW;
    float* wS0 = fS1 + FMK * FROW;            // 32 x 128
    float* wS1 = wS0 + FMK * Ff;
    float* ssS = wS1 + FMK * Ff;              // 256
    float* fB_[2] = {fS0, fS1};
    float* wB_[2] = {wS0, wS1};

    int which = blockIdx.y;
    const float* feat = which ? featB : featA;
    const float* bias = which ? biasB : biasA;
    const float* Wt   = which ? g_Wt2 : g_Wt1;
    float*       outp = which ? g_f2n : g_f1n;

    int t   = threadIdx.x;
    int p0  = blockIdx.x * 256;
    int b   = p0 / HW;
    int rem = p0 % HW;                        // full row: rem = h*256
    const float* fbase = feat + (size_t)b * Cc * HW + rem;

    int pg = t & 15, og = t >> 4;
    int o0 = og * 8;
    int pxb = pg * 4;                         // px chunks: pxb + c*64

    ssS[t] = 0.f;

    unsigned long long acc[8][8];
    #pragma unroll
    for (int i = 0; i < 8; i++)
        #pragma unroll
        for (int j = 0; j < 8; j++) acc[i][j] = 0ULL;

    auto load_tile = [&](int c0, int s) {
        #pragma unroll
        for (int it = 0; it < 8; it++) {               // 32 ch x 64 float4
            int idx = t + it * 256;
            int kc = idx >> 6, q = idx & 63;
            cp16(&fB_[s][kc * FROW + q * 4], &fbase[(size_t)(c0 + kc) * HW + q * 4]);
        }
        #pragma unroll
        for (int it = 0; it < 4; it++) {               // 32 ch x 32 float4
            int idx = t + it * 256;
            int kc = idx >> 5, q = idx & 31;
            cp16(&wB_[s][kc * Ff + q * 4], &Wt[(c0 + kc) * Ff + q * 4]);
        }
        cp_commit();
    };

    load_tile(0, 0);

    #pragma unroll
    for (int i = 0; i < Cc / FMK; i++) {
        if (i + 1 < Cc / FMK) { load_tile((i + 1) * FMK, (i + 1) & 1); cp_wait<1>(); }
        else                  { cp_wait<0>(); }
        __syncthreads();

        const float* fS = fB_[i & 1];
        const float* wS = wB_[i & 1];
        #pragma unroll
        for (int kk = 0; kk < FMK; kk++) {
            const float* fr = fS + kk * FROW + pxb;
            ulonglong2 fc0 = *(const ulonglong2*)&fr[0];
            ulonglong2 fc1 = *(const ulonglong2*)&fr[64];
            ulonglong2 fc2 = *(const ulonglong2*)&fr[128];
            ulonglong2 fc3 = *(const ulonglong2*)&fr[192];
            float4 w0 = *(const float4*)&wS[kk * Ff + o0];
            float4 w1 = *(const float4*)&wS[kk * Ff + o0 + 4];
            float wv[8] = {w0.x, w0.y, w0.z, w0.w, w1.x, w1.y, w1.z, w1.w};
            #pragma unroll
            for (int oi = 0; oi < 8; oi++) {
                unsigned long long ww = bcast2(wv[oi]);
                ffma2(acc[oi][0], ww, fc0.x);
                ffma2(acc[oi][1], ww, fc0.y);
                ffma2(acc[oi][2], ww, fc1.x);
                ffma2(acc[oi][3], ww, fc1.y);
                ffma2(acc[oi][4], ww, fc2.x);
                ffma2(acc[oi][5], ww, fc2.y);
                ffma2(acc[oi][6], ww, fc3.x);
                ffma2(acc[oi][7], ww, fc3.y);
            }
        }
        __syncthreads();
    }

    float bia[8];
    #pragma unroll
    for (int oi = 0; oi < 8; oi++) bia[oi] = bias[o0 + oi];

    // per-pixel sum of squares
    float ss[16];
    #pragma unroll
    for (int p = 0; p < 16; p++) ss[p] = 0.f;
    #pragma unroll
    for (int oi = 0; oi < 8; oi++)
        #pragma unroll
        for (int c = 0; c < 4; c++) {
            float v0, v1, v2, v3;
            unpack2(acc[oi][2 * c], v0, v1);
            unpack2(acc[oi][2 * c + 1], v2, v3);
            v0 += bia[oi]; v1 += bia[oi]; v2 += bia[oi]; v3 += bia[oi];
            ss[c * 4 + 0] += v0 * v0;
            ss[c * 4 + 1] += v1 * v1;
            ss[c * 4 + 2] += v2 * v2;
            ss[c * 4 + 3] += v3 * v3;
        }
    #pragma unroll
    for (int c = 0; c < 4; c++)
        #pragma unroll
        for (int q = 0; q < 4; q++)
            atomicAdd(&ssS[pxb + c * 64 + q], ss[c * 4 + q]);
    __syncthreads();

    float inv[16];
    #pragma unroll
    for (int c = 0; c < 4; c++)
        #pragma unroll
        for (int q = 0; q < 4; q++)
            inv[c * 4 + q] = 1.f / (sqrtf(ssS[pxb + c * 64 + q]) + 1e-8f);

    #pragma unroll
    for (int oi = 0; oi < 8; oi++) {
        float* op = outp + ((size_t)b * Ff + o0 + oi) * HW + rem + pxb;
        #pragma unroll
        for (int c = 0; c < 4; c++) {
            float v0, v1, v2, v3;
            unpack2(acc[oi][2 * c], v0, v1);
            unpack2(acc[oi][2 * c + 1], v2, v3);
            float4 sv = make_float4((v0 + bia[oi]) * inv[c * 4 + 0],
                                    (v1 + bia[oi]) * inv[c * 4 + 1],
                                    (v2 + bia[oi]) * inv[c * 4 + 2],
                                    (v3 + bia[oi]) * inv[c * 4 + 3]);
            *(float4*)&op[c * 64] = sv;
        }
    }
}

// ---------------- fused correlation + selector (cv prefetched via cp.async) ----------------
__global__ __launch_bounds__(224) void corrsel_kernel(const float* __restrict__ cv0,
                                                      const float* __restrict__ cv1,
                                                      const float* __restrict__ cv2,
                                                      float* __restrict__ out)
{
    // dynamic smem layout (floats):
    //   s1c : 64*68  = 4352  (f1 tile; tail reused: outS 3136, Msm 441, beta 3)
    //   s2c : 64*116 = 7424
    //   cvS : 3*49*64= 9408  (separate buffer -> prefetch overlaps Gram compute)
    //   wsm : 3*64   = 192
    float* s1c  = dynsm;
    float* s2c  = dynsm + 4352;
    float* cvS  = s2c + 7424;
    float* wsm  = cvS + 9408;
    float* outS = s1c;
    float* Msm  = s1c + 3136;
    float* betaS= Msm + 441;

    int t   = threadIdx.x;
    int blk = blockIdx.x;
    int bh  = blk >> 2;
    int x0  = (blk & 3) * 64;
    int b   = bh / Hh, h = bh % Hh;

    // prefetch cv tiles: overlap with phase-1 compute
    for (int idx = t; idx < 3 * CVC * 16; idx += 224) {    // 2352 float4
        int v = idx / (CVC * 16);
        int r = idx - v * (CVC * 16);
        int c = r >> 4, q = r & 15;
        const float* src = (v == 0 ? cv0 : (v == 1 ? cv1 : cv2));
        cp16(&cvS[(v * CVC + c) * 64 + q * 4],
             &src[((size_t)(b * CVC + c) * Hh + h) * Wd + x0 + q * 4]);
    }
    cp_commit();

    const float* f1 = g_f1n + (size_t)b * Ff * HW + (size_t)h * Wd;
    const float* f2 = g_f2n + (size_t)b * Ff * HW + (size_t)h * Wd;

    int xt = t & 15, j = t >> 4;       // j 0..13 (j==13 -> load-only helper)
    bool active = (j < 13);

    unsigned long long acc[4][2];
    #pragma unroll
    for (int i = 0; i < 4; i++) { acc[i][0] = 0ULL; acc[i][1] = 0ULL; }

    // ---- phase 1: banded Gram over 2 channel halves ----
    for (int half = 0; half < 2; half++) {
        __syncthreads();
        int cbase = half * 64;
        for (int idx = t; idx < 1024; idx += 224) {        // 64 ch x 16 float4
            int o = idx >> 4, q = idx & 15;
            *(float4*)&s1c[o * 68 + q * 4] =
                *(const float4*)&f1[(size_t)(cbase + o) * HW + x0 + q * 4];
        }
        for (int idx = t; idx < 1792; idx += 224) {        // 64 ch x 28 float4
            int o = idx / 28, q = idx - o * 28;
            int xg = x0 - RAD + q * 4;                     // OOB always whole-float4
            float4 vv = make_float4(0.f, 0.f, 0.f, 0.f);
            if (xg >= 0 && xg <= Wd - 4)
                vv = *(const float4*)&f2[(size_t)(cbase + o) * HW + xg];
            *(float4*)&s2c[o * 116 + q * 4] = vv;
        }
        __syncthreads();

        if (active) {
            #pragma unroll 4
            for (int o = 0; o < 64; o++) {
                float4 a = *(const float4*)&s1c[o * 68 + 4 * xt];
                ulonglong2 bb = *(const ulonglong2*)&s2c[o * 116 + 4 * (xt + j)];
                float av[4] = {a.x, a.y, a.z, a.w};
                #pragma unroll
                for (int i = 0; i < 4; i++) {
                    unsigned long long aa = bcast2(av[i]);
                    ffma2(acc[i][0], aa, bb.x);
                    ffma2(acc[i][1], aa, bb.y);
                }
            }
        }
    }

    __syncthreads();   // phase-1 reads of s1c/s2c done

    // ---- phase 2: stage corr tile; load M/beta; wait for cv prefetch ----
    if (active) {
        #pragma unroll
        for (int i = 0; i < 4; i++) {
            float vals[4];
            unpack2(acc[i][0], vals[0], vals[1]);
            unpack2(acc[i][1], vals[2], vals[3]);
            #pragma unroll
            for (int ip = 0; ip < 4; ip++) {
                int k = 48 - 4 * j + i - ip;
                if (k >= 0 && k <= 48)
                    outS[k * 64 + 4 * xt + i] = vals[ip];
            }
        }
    }
    for (int i = t; i < 9 * CVC; i += 224) Msm[i] = g_M[i];
    if (t < 3) betaS[t] = g_beta[t];
    cp_wait<0>();
    __syncthreads();

    // ---- phase 4: folded logits (192 threads: 3 logits x 64 px) ----
    if (t < 192) {
        int j2 = t >> 6;         // logit 0..2
        int x  = t & 63;
        float l = betaS[j2];
        const float* M0 = Msm + 0 * 3 * CVC + j2 * CVC;
        const float* M1 = Msm + 1 * 3 * CVC + j2 * CVC;
        const float* M2 = Msm + 2 * 3 * CVC + j2 * CVC;
        #pragma unroll 7
        for (int c = 0; c < CVC; c++) {
            l = fmaf(M0[c], cvS[(0 * CVC + c) * 64 + x],
                fmaf(M1[c], cvS[(1 * CVC + c) * 64 + x],
                fmaf(M2[c], cvS[(2 * CVC + c) * 64 + x], l)));
        }
        wsm[j2 * 64 + x] = l;
    }
    __syncthreads();

    // ---- phase 4b: softmax ----
    if (t < 64) {
        float l0 = wsm[t], l1 = wsm[64 + t], l2 = wsm[128 + t];
        float m  = fmaxf(l0, fmaxf(l1, l2));
        float e0 = expf(l0 - m), e1 = expf(l1 - m), e2 = expf(l2 - m);
        float inv = 1.f / (e0 + e1 + e2);
        float w0 = e0 * inv, w1 = e1 * inv, w2 = e2 * inv;
        wsm[t] = w0; wsm[64 + t] = w1; wsm[128 + t] = w2;
        float* wout = out + 2 * NC_ + ((size_t)b * 3 * Hh + h) * Wd + x0 + t;
        wout[0]              = w0;
        wout[(size_t)HW]     = w1;
        wout[(size_t)2 * HW] = w2;
    }
    __syncthreads();

    // ---- phase 5: final = corr + w·cv ; write final + init_corr ----
    for (int idx = t; idx < CVC * 16; idx += 224) {        // 784 float4
        int k = idx >> 4, q = idx & 15;
        float4 corr4 = *(const float4*)&outS[k * 64 + q * 4];
        float4 a0 = *(const float4*)&cvS[(0 * CVC + k) * 64 + q * 4];
        float4 a1 = *(const float4*)&cvS[(1 * CVC + k) * 64 + q * 4];
        float4 a2 = *(const float4*)&cvS[(2 * CVC + k) * 64 + q * 4];
        float4 w0 = *(const float4*)&wsm[0 * 64 + q * 4];
        float4 w1 = *(const float4*)&wsm[1 * 64 + q * 4];
        float4 w2 = *(const float4*)&wsm[2 * 64 + q * 4];
        float4 fin;
        fin.x = corr4.x + fmaf(w0.x, a0.x, fmaf(w1.x, a1.x, w2.x * a2.x));
        fin.y = corr4.y + fmaf(w0.y, a0.y, fmaf(w1.y, a1.y, w2.y * a2.y));
        fin.z = corr4.z + fmaf(w0.z, a0.z, fmaf(w1.z, a1.z, w2.z * a2.z));
        fin.w = corr4.w + fmaf(w0.w, a0.w, fmaf(w1.w, a1.w, w2.w * a2.w));
        size_t off = ((size_t)(b * CVC + k) * Hh + h) * Wd + x0 + q * 4;
        *(float4*)&out[off]       = fin;
        *(float4*)&out[NC_ + off] = corr4;
    }
}

// ---------------- launch ----------------
extern "C" void kernel_launch(void* const* d_in, const int* in_sizes, int n_in,
                              void* d_out, int out_size)
{
    const float* feat_l1 = (const float*)d_in[0];
    const float* feat_r1 = (const float*)d_in[1];
    const float* cv0     = (const float*)d_in[2];
    const float* cv1     = (const float*)d_in[3];
    const float* cv2     = (const float*)d_in[4];
    const float* W_f1    = (const float*)d_in[5];
    const float* b_f1    = (const float*)d_in[6];
    const float* W_f2    = (const float*)d_in[7];
    const float* b_f2    = (const float*)d_in[8];
    const float* W_geo   = (const float*)d_in[9];
    const float* b_geo   = (const float*)d_in[10];
    const float* W_sel   = (const float*)d_in[11];
    const float* b_sel   = (const float*)d_in[12];
    float* out = (float*)d_out;

    prep_kernel<<<20, 256>>>(W_f1, W_f2, W_geo, b_geo, W_sel, b_sel);

    int fm_smem = (2 * FMK * FROW + 2 * FMK * Ff + 256) * (int)sizeof(float); // ~101.4KB
    static int fm_set = 0;
    if (!fm_set) {
        cudaFuncSetAttribute(fmap_kernel, cudaFuncAttributeMaxDynamicSharedMemorySize, fm_smem);
        fm_set = 1;
    }
    fmap_kernel<<<dim3(NPIX / 256, 2), 256, fm_smem>>>(feat_l1, feat_r1, b_f1, b_f2);

    int cs_smem = (4352 + 7424 + 9408 + 192) * (int)sizeof(float);            // ~85.5KB
    static int cs_set = 0;
    if (!cs_set) {
        cudaFuncSetAttribute(corrsel_kernel, cudaFuncAttributeMaxDynamicSharedMemorySize, cs_smem);
        cs_set = 1;
    }
    corrsel_kernel<<<Bn * Hh * (Wd / 64), 224, cs_smem>>>(cv0, cv1, cv2, out);
}

// round 10
// speedup vs baseline: 1.1037x; 1.1037x over previous
#include <cuda_runtime.h>
#include <cuda_bf16.h>
#include <cstdint>
#include <cstddef>

// ---------------- problem constants ----------------
#define Bn   4
#define Cc   128
#define Hh   128
#define Wd   256
#define HW   (Hh*Wd)          // 32768
#define Ff   128
#define CVC  49
#define RAD  24
#define NPIX (Bn*HW)          // 131072
static const size_t NC_ = (size_t)Bn * CVC * HW;  // elements per corr-like tensor

// ---------------- device scratch (static, no allocation) ----------------
__device__ float g_f1n[(size_t)NPIX * Ff];   // [B][F][H][W]
__device__ float g_f2n[(size_t)NPIX * Ff];
__device__ float g_M[9 * CVC];               // [i][j][c], i=volume, j=logit
__device__ float g_beta[3];
// W as bf16 hi/lo, plain [o][c] layout
__device__ uint16_t g_W1h[Ff * Cc];
__device__ uint16_t g_W1l[Ff * Cc];
__device__ uint16_t g_W2h[Ff * Cc];
__device__ uint16_t g_W2l[Ff * Cc];

// ---------------- helpers ----------------
__device__ __forceinline__ unsigned long long bcast2(float v) {
    unsigned long long r; asm("mov.b64 %0, {%1,%1};" : "=l"(r) : "f"(v)); return r;
}
__device__ __forceinline__ void unpack2(unsigned long long p, float& lo, float& hi) {
    asm("mov.b64 {%0,%1}, %2;" : "=f"(lo), "=f"(hi) : "l"(p));
}
__device__ __forceinline__ void ffma2(unsigned long long& acc, unsigned long long a, unsigned long long b) {
    asm("fma.rn.f32x2 %0, %1, %2, %0;" : "+l"(acc) : "l"(a), "l"(b));
}
__device__ __forceinline__ void cp16(void* smem_dst, const void* gmem_src) {
    unsigned int s = (unsigned int)__cvta_generic_to_shared(smem_dst);
    asm volatile("cp.async.cg.shared.global [%0], [%1], 16;" :: "r"(s), "l"(gmem_src));
}
__device__ __forceinline__ void cp_commit() { asm volatile("cp.async.commit_group;"); }
template <int N>
__device__ __forceinline__ void cp_wait() { asm volatile("cp.async.wait_group %0;" :: "n"(N)); }

// bf16 warp MMA m16n8k16, A row-major, B col-major (B stored [n][k]), fp32 accum.
__device__ __forceinline__ void mma16816(float* d, const uint32_t* a, const uint32_t* b) {
    asm volatile("mma.sync.aligned.m16n8k16.row.col.f32.bf16.bf16.f32 "
                 "{%0,%1,%2,%3}, {%4,%5,%6,%7}, {%8,%9}, {%0,%1,%2,%3};"
                 : "+f"(d[0]), "+f"(d[1]), "+f"(d[2]), "+f"(d[3])
                 : "r"(a[0]), "r"(a[1]), "r"(a[2]), "r"(a[3]), "r"(b[0]), "r"(b[1]));
}

// ---------------- prep: W bf16 hi/lo + selector fold ----------------
// blocks 0..7: W conversion; 8..10: M per volume; 11: beta.
__global__ void prep_kernel(const float* __restrict__ Wf1, const float* __restrict__ Wf2,
                            const float* __restrict__ Wgeo, const float* __restrict__ bgeo,
                            const float* __restrict__ Wsel, const float* __restrict__ bsel)
{
    int blk = blockIdx.x, t = threadIdx.x;
    if (blk < 8) {
        #pragma unroll
        for (int it = 0; it < 8; it++) {
            int idx = blk * 2048 + it * 256 + t;        // 0..16383, layout [o][c]
            float v1 = Wf1[idx];
            __nv_bfloat16 h1 = __float2bfloat16(v1);
            __nv_bfloat16 l1 = __float2bfloat16(v1 - __bfloat162float(h1));
            g_W1h[idx] = *(uint16_t*)&h1;
            g_W1l[idx] = *(uint16_t*)&l1;
            float v2 = Wf2[idx];
            __nv_bfloat16 h2 = __float2bfloat16(v2);
            __nv_bfloat16 l2 = __float2bfloat16(v2 - __bfloat162float(h2));
            g_W2h[idx] = *(uint16_t*)&h2;
            g_W2l[idx] = *(uint16_t*)&l2;
        }
    } else if (blk < 11) {
        int i = blk - 8;                             // volume index
        for (int r = t; r < 3 * CVC; r += 256) {     // j*CVC + c
            int j = r / CVC, c = r % CVC;
            float s = 0.f;
            #pragma unroll 8
            for (int m = 0; m < 96; m++)
                s += Wsel[j * 288 + i * 96 + m] * Wgeo[m * CVC + c];
            g_M[i * 3 * CVC + j * CVC + c] = s;
        }
    } else {
        if (t < 3) {
            float s = bsel[t];
            for (int q = 0; q < 288; q++)
                s += Wsel[t * 288 + q] * bgeo[q % 96];
            g_beta[t] = s;
        }
    }
}

// ---------------- fmap via HMMA: D[px][o] = feat @ W^T, 3-term bf16 split ----------------
// CTA: 128px x 128o x K=128. 8 warps (4m x 2n); warp tile 32px x 64o.
// Fragment loads straight from smem per PTX m16n8k16 layout; row stride 136 bf16
// -> banks 4*row+tig: conflict-free. Epilogue: bias + per-px L2 norm
// (shfl + smem atomics) + smem-staged coalesced stores.
#define ATS 17408            // uint16 elems per 128x136 tile
#define FM_SMEM_BYTES 140800

extern __shared__ float dynsm[];

__global__ __launch_bounds__(256) void fmap_kernel(
    const float* __restrict__ featA, const float* __restrict__ featB,
    const float* __restrict__ biasA, const float* __restrict__ biasB)
{
    char* smc = (char*)dynsm;
    uint16_t* sAh = (uint16_t*)smc;
    uint16_t* sAl = sAh + ATS;
    uint16_t* sWh = sAh + 2 * ATS;
    uint16_t* sWl = sAh + 3 * ATS;
    float* biasS = (float*)(smc + 4 * ATS * 2);          // 139264
    float* ssS   = biasS + 128;
    float* outSt = (float*)smc;                          // reuses sAh/sAl (67.6KB <= 69.6KB)

    int which = blockIdx.y;
    const float* feat = which ? featB : featA;
    const float* bias = which ? biasB : biasA;
    const uint16_t* gWh = which ? g_W2h : g_W1h;
    const uint16_t* gWl = which ? g_W2l : g_W1l;
    float* outp = which ? g_f2n : g_f1n;

    int t   = threadIdx.x;
    int wid = t >> 5, lane = t & 31;
    int gid = lane >> 2, tig = lane & 3;
    int warp_m = wid & 3, warp_n = wid >> 2;
    int p0  = blockIdx.x * 128;
    int b   = p0 / HW;
    int rem = p0 % HW;
    const float* fbase = feat + (size_t)b * Cc * HW + rem;

    if (t < 128) { biasS[t] = bias[t]; ssS[t] = 0.f; }

    // W tiles: async 16B copies, row-major [o][c] -> padded stride 136
    #pragma unroll
    for (int it = 0; it < 8; it++) {
        int i = t + it * 256;                  // 2048 chunks of 8 bf16
        int row = i >> 4, c8 = i & 15;
        cp16(sWh + row * 136 + c8 * 8, gWh + i * 8);
        cp16(sWl + row * 136 + c8 * 8, gWl + i * 8);
    }
    cp_commit();

    // feat tile: read [c][px] coalesced, split to bf16 hi/lo, write [px][c]
    #pragma unroll
    for (int it = 0; it < 16; it++) {
        int idx = t + it * 256;                // 4096 float4
        int c = idx >> 5, q = idx & 31;
        float4 v = *(const float4*)&fbase[(size_t)c * HW + q * 4];
        float vv[4] = {v.x, v.y, v.z, v.w};
        #pragma unroll
        for (int e = 0; e < 4; e++) {
            int px = q * 4 + e;
            __nv_bfloat16 h = __float2bfloat16(vv[e]);
            __nv_bfloat16 l = __float2bfloat16(vv[e] - __bfloat162float(h));
            sAh[px * 136 + c] = *(uint16_t*)&h;
            sAl[px * 136 + c] = *(uint16_t*)&l;
        }
    }
    cp_wait<0>();
    __syncthreads();

    float acc[2][8][4];
    #pragma unroll
    for (int mt = 0; mt < 2; mt++)
        #pragma unroll
        for (int nt = 0; nt < 8; nt++)
            #pragma unroll
            for (int r = 0; r < 4; r++) acc[mt][nt][r] = 0.f;

    const uint16_t* As[3] = {sAh, sAh, sAl};
    const uint16_t* Bs[3] = {sWh, sWl, sWh};

    #pragma unroll
    for (int p = 0; p < 3; p++) {
        const uint16_t* A = As[p];
        const uint16_t* B = Bs[p];
        #pragma unroll
        for (int ks = 0; ks < 8; ks++) {
            int kb = ks * 16 + 2 * tig;
            uint32_t afr[2][4];
            #pragma unroll
            for (int mt = 0; mt < 2; mt++) {
                int row = warp_m * 32 + mt * 16 + gid;
                afr[mt][0] = *(const uint32_t*)(A + row * 136 + kb);
                afr[mt][1] = *(const uint32_t*)(A + (row + 8) * 136 + kb);
                afr[mt][2] = *(const uint32_t*)(A + row * 136 + kb + 8);
                afr[mt][3] = *(const uint32_t*)(A + (row + 8) * 136 + kb + 8);
            }
            #pragma unroll
            for (int nt = 0; nt < 8; nt++) {
                int orow = warp_n * 64 + nt * 8 + gid;
                uint32_t bfr[2];
                bfr[0] = *(const uint32_t*)(B + orow * 136 + kb);
                bfr[1] = *(const uint32_t*)(B + orow * 136 + kb + 8);
                mma16816(acc[0][nt], afr[0], bfr);
                mma16816(acc[1][nt], afr[1], bfr);
            }
        }
    }

    // ---- epilogue: bias, per-pixel L2 norm, staged coalesced stores ----
    #pragma unroll
    for (int nt = 0; nt < 8; nt++) {
        int ob2 = warp_n * 64 + nt * 8 + 2 * tig;
        float bi0 = biasS[ob2], bi1 = biasS[ob2 + 1];
        #pragma unroll
        for (int mt = 0; mt < 2; mt++) {
            acc[mt][nt][0] += bi0; acc[mt][nt][1] += bi1;
            acc[mt][nt][2] += bi0; acc[mt][nt][3] += bi1;
        }
    }

    float s0[2] = {0.f, 0.f}, s1[2] = {0.f, 0.f};   // rows gid, gid+8 per mt
    #pragma unroll
    for (int mt = 0; mt < 2; mt++)
        #pragma unroll
        for (int nt = 0; nt < 8; nt++) {
            s0[mt] += acc[mt][nt][0] * acc[mt][nt][0] + acc[mt][nt][1] * acc[mt][nt][1];
            s1[mt] += acc[mt][nt][2] * acc[mt][nt][2] + acc[mt][nt][3] * acc[mt][nt][3];
        }
    #pragma unroll
    for (int off = 1; off <= 2; off <<= 1) {
        s0[0] += __shfl_xor_sync(0xFFFFFFFF, s0[0], off);
        s0[1] += __shfl_xor_sync(0xFFFFFFFF, s0[1], off);
        s1[0] += __shfl_xor_sync(0xFFFFFFFF, s1[0], off);
        s1[1] += __shfl_xor_sync(0xFFFFFFFF, s1[1], off);
    }
    if (tig == 0) {
        #pragma unroll
        for (int mt = 0; mt < 2; mt++) {
            int px = warp_m * 32 + mt * 16 + gid;
            atomicAdd(&ssS[px], s0[mt]);
            atomicAdd(&ssS[px + 8], s1[mt]);
        }
    }
    __syncthreads();
    if (t < 128) ssS[t] = 1.f / (sqrtf(ssS[t]) + 1e-8f);
    __syncthreads();

    #pragma unroll
    for (int mt = 0; mt < 2; mt++) {
        int px = warp_m * 32 + mt * 16 + gid;
        float iv0 = ssS[px], iv1 = ssS[px + 8];
        #pragma unroll
        for (int nt = 0; nt < 8; nt++) {
            int o = warp_n * 64 + nt * 8 + 2 * tig;
            outSt[o * 132 + px]            = acc[mt][nt][0] * iv0;
            outSt[(o + 1) * 132 + px]      = acc[mt][nt][1] * iv0;
            outSt[o * 132 + px + 8]        = acc[mt][nt][2] * iv1;
            outSt[(o + 1) * 132 + px + 8]  = acc[mt][nt][3] * iv1;
        }
    }
    __syncthreads();

    #pragma unroll
    for (int it = 0; it < 16; it++) {
        int idx = t + it * 256;                // 4096 float4
        int o = idx >> 5, q = idx & 31;
        float4 v = *(const float4*)&outSt[o * 132 + q * 4];
        *(float4*)&outp[((size_t)b * Ff + o) * HW + rem + q * 4] = v;
    }
}

// ---------------- fused correlation + selector (R5-verbatim) ----------------
__global__ __launch_bounds__(224) void corrsel_kernel(const float* __restrict__ cv0,
                                                      const float* __restrict__ cv1,
                                                      const float* __restrict__ cv2,
                                                      float* __restrict__ out)
{
    float* s1c  = dynsm;
    float* s2c  = dynsm + 4352;
    float* cvS  = s2c + 7424;
    float* wsm  = cvS + 9408;
    float* outS = s1c;
    float* Msm  = s1c + 3136;
    float* betaS= Msm + 441;

    int t   = threadIdx.x;
    int blk = blockIdx.x;
    int bh  = blk >> 2;
    int x0  = (blk & 3) * 64;
    int b   = bh / Hh, h = bh % Hh;

    for (int idx = t; idx < 3 * CVC * 16; idx += 224) {
        int v = idx / (CVC * 16);
        int r = idx - v * (CVC * 16);
        int c = r >> 4, q = r & 15;
        const float* src = (v == 0 ? cv0 : (v == 1 ? cv1 : cv2));
        cp16(&cvS[(v * CVC + c) * 64 + q * 4],
             &src[((size_t)(b * CVC + c) * Hh + h) * Wd + x0 + q * 4]);
    }
    cp_commit();

    const float* f1 = g_f1n + (size_t)b * Ff * HW + (size_t)h * Wd;
    const float* f2 = g_f2n + (size_t)b * Ff * HW + (size_t)h * Wd;

    int xt = t & 15, j = t >> 4;
    bool active = (j < 13);

    unsigned long long acc[4][2];
    #pragma unroll
    for (int i = 0; i < 4; i++) { acc[i][0] = 0ULL; acc[i][1] = 0ULL; }

    for (int half = 0; half < 2; half++) {
        __syncthreads();
        int cbase = half * 64;
        for (int idx = t; idx < 1024; idx += 224) {
            int o = idx >> 4, q = idx & 15;
            *(float4*)&s1c[o * 68 + q * 4] =
                *(const float4*)&f1[(size_t)(cbase + o) * HW + x0 + q * 4];
        }
        for (int idx = t; idx < 1792; idx += 224) {
            int o = idx / 28, q = idx - o * 28;
            int xg = x0 - RAD + q * 4;
            float4 vv = make_float4(0.f, 0.f, 0.f, 0.f);
            if (xg >= 0 && xg <= Wd - 4)
                vv = *(const float4*)&f2[(size_t)(cbase + o) * HW + xg];
            *(float4*)&s2c[o * 116 + q * 4] = vv;
        }
        __syncthreads();

        if (active) {
            #pragma unroll 4
            for (int o = 0; o < 64; o++) {
                float4 a = *(const float4*)&s1c[o * 68 + 4 * xt];
                ulonglong2 bb = *(const ulonglong2*)&s2c[o * 116 + 4 * (xt + j)];
                float av[4] = {a.x, a.y, a.z, a.w};
                #pragma unroll
                for (int i = 0; i < 4; i++) {
                    unsigned long long aa = bcast2(av[i]);
                    ffma2(acc[i][0], aa, bb.x);
                    ffma2(acc[i][1], aa, bb.y);
                }
            }
        }
    }

    __syncthreads();

    if (active) {
        #pragma unroll
        for (int i = 0; i < 4; i++) {
            float vals[4];
            unpack2(acc[i][0], vals[0], vals[1]);
            unpack2(acc[i][1], vals[2], vals[3]);
            #pragma unroll
            for (int ip = 0; ip < 4; ip++) {
                int k = 48 - 4 * j + i - ip;
                if (k >= 0 && k <= 48)
                    outS[k * 64 + 4 * xt + i] = vals[ip];
            }
        }
    }
    for (int i = t; i < 9 * CVC; i += 224) Msm[i] = g_M[i];
    if (t < 3) betaS[t] = g_beta[t];
    cp_wait<0>();
    __syncthreads();

    if (t < 192) {
        int j2 = t >> 6;
        int x  = t & 63;
        float l = betaS[j2];
        const float* M0 = Msm + 0 * 3 * CVC + j2 * CVC;
        const float* M1 = Msm + 1 * 3 * CVC + j2 * CVC;
        const float* M2 = Msm + 2 * 3 * CVC + j2 * CVC;
        #pragma unroll 7
        for (int c = 0; c < CVC; c++) {
            l = fmaf(M0[c], cvS[(0 * CVC + c) * 64 + x],
                fmaf(M1[c], cvS[(1 * CVC + c) * 64 + x],
                fmaf(M2[c], cvS[(2 * CVC + c) * 64 + x], l)));
        }
        wsm[j2 * 64 + x] = l;
    }
    __syncthreads();

    if (t < 64) {
        float l0 = wsm[t], l1 = wsm[64 + t], l2 = wsm[128 + t];
        float m  = fmaxf(l0, fmaxf(l1, l2));
        float e0 = expf(l0 - m), e1 = expf(l1 - m), e2 = expf(l2 - m);
        float inv = 1.f / (e0 + e1 + e2);
        float w0 = e0 * inv, w1 = e1 * inv, w2 = e2 * inv;
        wsm[t] = w0; wsm[64 + t] = w1; wsm[128 + t] = w2;
        float* wout = out + 2 * NC_ + ((size_t)b * 3 * Hh + h) * Wd + x0 + t;
        wout[0]              = w0;
        wout[(size_t)HW]     = w1;
        wout[(size_t)2 * HW] = w2;
    }
    __syncthreads();

    for (int idx = t; idx < CVC * 16; idx += 224) {
        int k = idx >> 4, q = idx & 15;
        float4 corr4 = *(const float4*)&outS[k * 64 + q * 4];
        float4 a0 = *(const float4*)&cvS[(0 * CVC + k) * 64 + q * 4];
        float4 a1 = *(const float4*)&cvS[(1 * CVC + k) * 64 + q * 4];
        float4 a2 = *(const float4*)&cvS[(2 * CVC + k) * 64 + q * 4];
        float4 w0 = *(const float4*)&wsm[0 * 64 + q * 4];
        float4 w1 = *(const float4*)&wsm[1 * 64 + q * 4];
        float4 w2 = *(const float4*)&wsm[2 * 64 + q * 4];
        float4 fin;
        fin.x = corr4.x + fmaf(w0.x, a0.x, fmaf(w1.x, a1.x, w2.x * a2.x));
        fin.y = corr4.y + fmaf(w0.y, a0.y, fmaf(w1.y, a1.y, w2.y * a2.y));
        fin.z = corr4.z + fmaf(w0.z, a0.z, fmaf(w1.z, a1.z, w2.z * a2.z));
        fin.w = corr4.w + fmaf(w0.w, a0.w, fmaf(w1.w, a1.w, w2.w * a2.w));
        size_t off = ((size_t)(b * CVC + k) * Hh + h) * Wd + x0 + q * 4;
        *(float4*)&out[off]       = fin;
        *(float4*)&out[NC_ + off] = corr4;
    }
}

// ---------------- launch ----------------
extern "C" void kernel_launch(void* const* d_in, const int* in_sizes, int n_in,
                              void* d_out, int out_size)
{
    const float* feat_l1 = (const float*)d_in[0];
    const float* feat_r1 = (const float*)d_in[1];
    const float* cv0     = (const float*)d_in[2];
    const float* cv1     = (const float*)d_in[3];
    const float* cv2     = (const float*)d_in[4];
    const float* W_f1    = (const float*)d_in[5];
    const float* b_f1    = (const float*)d_in[6];
    const float* W_f2    = (const float*)d_in[7];
    const float* b_f2    = (const float*)d_in[8];
    const float* W_geo   = (const float*)d_in[9];
    const float* b_geo   = (const float*)d_in[10];
    const float* W_sel   = (const float*)d_in[11];
    const float* b_sel   = (const float*)d_in[12];
    float* out = (float*)d_out;

    prep_kernel<<<12, 256>>>(W_f1, W_f2, W_geo, b_geo, W_sel, b_sel);

    static int fm_set = 0;
    if (!fm_set) {
        cudaFuncSetAttribute(fmap_kernel, cudaFuncAttributeMaxDynamicSharedMemorySize, FM_SMEM_BYTES);
        fm_set = 1;
    }
    fmap_kernel<<<dim3(NPIX / 128, 2), 256, FM_SMEM_BYTES>>>(feat_l1, feat_r1, b_f1, b_f2);

    int cs_smem = (4352 + 7424 + 9408 + 192) * (int)sizeof(float);            // ~85.5KB
    static int cs_set = 0;
    if (!cs_set) {
        cudaFuncSetAttribute(corrsel_kernel, cudaFuncAttributeMaxDynamicSharedMemorySize, cs_smem);
        cs_set = 1;
    }
    corrsel_kernel<<<Bn * Hh * (Wd / 64), 224, cs_smem>>>(cv0, cv1, cv2, out);
}

// round 11
// speedup vs baseline: 1.5123x; 1.3702x over previous
#include <cuda_runtime.h>
#include <cuda_bf16.h>
#include <cstdint>
#include <cstddef>

// ---------------- problem constants ----------------
#define Bn   4
#define Cc   128
#define Hh   128
#define Wd   256
#define HW   (Hh*Wd)          // 32768
#define Ff   128
#define CVC  49
#define RAD  24
#define NPIX (Bn*HW)          // 131072
static const size_t NC_ = (size_t)Bn * CVC * HW;  // elements per corr-like tensor

// ---------------- device scratch (static, no allocation) ----------------
__device__ float g_f1n[(size_t)NPIX * Ff];   // [B][F][H][W]
__device__ float g_f2n[(size_t)NPIX * Ff];
__device__ float g_M[9 * CVC];               // [i][j][c], i=volume, j=logit
__device__ float g_beta[3];

// ---------------- helpers ----------------
__device__ __forceinline__ unsigned long long bcast2(float v) {
    unsigned long long r; asm("mov.b64 %0, {%1,%1};" : "=l"(r) : "f"(v)); return r;
}
__device__ __forceinline__ void unpack2(unsigned long long p, float& lo, float& hi) {
    asm("mov.b64 {%0,%1}, %2;" : "=f"(lo), "=f"(hi) : "l"(p));
}
__device__ __forceinline__ void ffma2(unsigned long long& acc, unsigned long long a, unsigned long long b) {
    asm("fma.rn.f32x2 %0, %1, %2, %0;" : "+l"(acc) : "l"(a), "l"(b));
}
__device__ __forceinline__ void cp16(void* smem_dst, const void* gmem_src) {
    unsigned int s = (unsigned int)__cvta_generic_to_shared(smem_dst);
    asm volatile("cp.async.cg.shared.global [%0], [%1], 16;" :: "r"(s), "l"(gmem_src));
}
__device__ __forceinline__ void cp_commit() { asm volatile("cp.async.commit_group;"); }
template <int N>
__device__ __forceinline__ void cp_wait() { asm volatile("cp.async.wait_group %0;" :: "n"(N)); }

// bf16 warp MMA m16n8k16, A row-major, B col-major (B stored [n][k]), fp32 accum.
__device__ __forceinline__ void mma16816(float* d, const uint32_t* a, const uint32_t* b) {
    asm volatile("mma.sync.aligned.m16n8k16.row.col.f32.bf16.bf16.f32 "
                 "{%0,%1,%2,%3}, {%4,%5,%6,%7}, {%8,%9}, {%0,%1,%2,%3};"
                 : "+f"(d[0]), "+f"(d[1]), "+f"(d[2]), "+f"(d[3])
                 : "r"(a[0]), "r"(a[1]), "r"(a[2]), "r"(a[3]), "r"(b[0]), "r"(b[1]));
}

// split two fp32 into packed-bf16x2 hi and lo words (low half = first element)
__device__ __forceinline__ void split2(float a, float b, uint32_t& h, uint32_t& l) {
    __nv_bfloat16 ha = __float2bfloat16(a), hb = __float2bfloat16(b);
    float ra = a - __bfloat162float(ha), rb = b - __bfloat162float(hb);
    __nv_bfloat16 la = __float2bfloat16(ra), lb = __float2bfloat16(rb);
    h = (uint32_t)*(uint16_t*)&ha | ((uint32_t)*(uint16_t*)&hb << 16);
    l = (uint32_t)*(uint16_t*)&la | ((uint32_t)*(uint16_t*)&lb << 16);
}
__device__ __forceinline__ uint32_t packh(float a, float b) {
    __nv_bfloat16 ha = __float2bfloat16(a), hb = __float2bfloat16(b);
    return (uint32_t)*(uint16_t*)&ha | ((uint32_t)*(uint16_t*)&hb << 16);
}
__device__ __forceinline__ uint32_t packl(float a, float b) {
    __nv_bfloat16 ha = __float2bfloat16(a), hb = __float2bfloat16(b);
    float ra = a - __bfloat162float(ha), rb = b - __bfloat162float(hb);
    __nv_bfloat16 la = __float2bfloat16(ra), lb = __float2bfloat16(rb);
    return (uint32_t)*(uint16_t*)&la | ((uint32_t)*(uint16_t*)&lb << 16);
}

// ---------------- prep: selector fold only (W handled inside fmap) ----------------
__global__ void prep_kernel(const float* __restrict__ Wgeo, const float* __restrict__ bgeo,
                            const float* __restrict__ Wsel, const float* __restrict__ bsel)
{
    int blk = blockIdx.x, t = threadIdx.x;
    if (blk < 3) {
        int i = blk;                                 // volume index
        for (int r = t; r < 3 * CVC; r += 256) {     // j*CVC + c
            int j = r / CVC, c = r % CVC;
            float s = 0.f;
            #pragma unroll 8
            for (int m = 0; m < 96; m++)
                s += Wsel[j * 288 + i * 96 + m] * Wgeo[m * CVC + c];
            g_M[i * 3 * CVC + j * CVC + c] = s;
        }
    } else {
        if (t < 3) {
            float s = bsel[t];
            for (int q = 0; q < 288; q++)
                s += Wsel[t * 288 + q] * bgeo[q % 96];
            g_beta[t] = s;
        }
    }
}

// ---------------- fmap via HMMA, K-pipelined, fp32 A staging ----------------
// CTA: 128px x 128o; K in 4 chunks of 32 (cp.async 2-stage). 8 warps (4m x 2n).
// A staged fp32 in gmem layout [c][px] (direct cp.async, no reformat); bf16 hi/lo
// split done in registers at fragment build. W converted inline from fp32 input.
// 3-term split: Ah*Wh + Al*Wh + Ah*Wl, fp32 accum.
#define WH_OFF   0            // uint16[128][136]  34816 B
#define WL_OFF   34816        // uint16[128][136]  34816 B
#define A_OFF    69632        // fp32 [2][32][132] 2x16896 B
#define BIAS_OFF 103424       // fp32[128]
#define SS_OFF   103936       // fp32[128]
#define FM_SMEM_BYTES 104448

extern __shared__ float dynsm[];

__global__ __launch_bounds__(256, 2) void fmap_kernel(
    const float* __restrict__ featA, const float* __restrict__ featB,
    const float* __restrict__ WfA,   const float* __restrict__ WfB,
    const float* __restrict__ biasA, const float* __restrict__ biasB)
{
    char* smc = (char*)dynsm;
    uint16_t* sWh = (uint16_t*)(smc + WH_OFF);
    uint16_t* sWl = (uint16_t*)(smc + WL_OFF);
    float* sA0   = (float*)(smc + A_OFF);
    float* sA1   = sA0 + 32 * 132;
    float* biasS = (float*)(smc + BIAS_OFF);
    float* ssS   = (float*)(smc + SS_OFF);
    float* outSt = (float*)smc;               // reuses W region post-compute (67.6KB<=69.6KB)
    float* stg[2] = {sA0, sA1};

    int which = blockIdx.y;
    const float* feat = which ? featB : featA;
    const float* Wsrc = which ? WfB : WfA;
    const float* bias = which ? biasB : biasA;
    float* outp = which ? g_f2n : g_f1n;

    int t    = threadIdx.x;
    int wid  = t >> 5, lane = t & 31;
    int gid  = lane >> 2, tig = lane & 3;
    int warp_m = wid & 3, warp_n = wid >> 2;
    int p0  = blockIdx.x * 128;
    int b   = p0 / HW;
    int rem = p0 % HW;
    const float* fbase = feat + (size_t)b * Cc * HW + rem;

    if (t < 128) { biasS[t] = bias[t]; ssS[t] = 0.f; }

    // A chunk 0 prefetch (32c x 32 float4 = 1024 cp16)
    #pragma unroll
    for (int it = 0; it < 4; it++) {
        int idx = t + it * 256;
        int c = idx >> 5, q = idx & 31;
        cp16(&sA0[c * 132 + q * 4], &fbase[(size_t)c * HW + q * 4]);
    }
    cp_commit();

    // W: load fp32, split, store packed rows (stride 136 halfwords)
    #pragma unroll
    for (int it = 0; it < 16; it++) {
        int idx = t + it * 256;                 // 4096 float4
        int o = idx >> 5, q = idx & 31;
        float4 v = *(const float4*)&Wsrc[o * Cc + q * 4];
        uint32_t h01, l01, h23, l23;
        split2(v.x, v.y, h01, l01);
        split2(v.z, v.w, h23, l23);
        uint32_t* ph = (uint32_t*)(sWh + o * 136 + q * 4);
        uint32_t* pl = (uint32_t*)(sWl + o * 136 + q * 4);
        ph[0] = h01; ph[1] = h23;
        pl[0] = l01; pl[1] = l23;
    }

    float acc[2][8][4];
    #pragma unroll
    for (int mt = 0; mt < 2; mt++)
        #pragma unroll
        for (int nt = 0; nt < 8; nt++)
            #pragma unroll
            for (int r = 0; r < 4; r++) acc[mt][nt][r] = 0.f;

    int row0 = warp_m * 32 + gid;              // mt=0 row; mt=1 adds 16

    #pragma unroll
    for (int ch = 0; ch < 4; ch++) {
        if (ch < 3) {
            float* dst = stg[(ch + 1) & 1];
            const float* src = fbase + (size_t)(ch + 1) * 32 * HW;
            #pragma unroll
            for (int it = 0; it < 4; it++) {
                int idx = t + it * 256;
                int c = idx >> 5, q = idx & 31;
                cp16(&dst[c * 132 + q * 4], &src[(size_t)c * HW + q * 4]);
            }
            cp_commit();
            cp_wait<1>();
        } else {
            cp_wait<0>();
        }
        __syncthreads();

        const float* A = stg[ch & 1];
        #pragma unroll
        for (int ks = 0; ks < 2; ks++) {
            int kb = ks * 16 + 2 * tig;        // k within chunk
            uint32_t ah[2][4], al[2][4];
            #pragma unroll
            for (int mt = 0; mt < 2; mt++) {
                int row = row0 + mt * 16;
                float f0 = A[kb * 132 + row],        f1 = A[(kb + 1) * 132 + row];
                float f2 = A[kb * 132 + row + 8],    f3 = A[(kb + 1) * 132 + row + 8];
                float f4 = A[(kb + 8) * 132 + row],  f5 = A[(kb + 9) * 132 + row];
                float f6 = A[(kb + 8) * 132 + row + 8], f7 = A[(kb + 9) * 132 + row + 8];
                split2(f0, f1, ah[mt][0], al[mt][0]);
                split2(f2, f3, ah[mt][1], al[mt][1]);
                split2(f4, f5, ah[mt][2], al[mt][2]);
                split2(f6, f7, ah[mt][3], al[mt][3]);
            }
            int kw = ch * 32 + kb;             // k within full K=128 for W
            #pragma unroll
            for (int nt = 0; nt < 8; nt++) {
                int orow = warp_n * 64 + nt * 8 + gid;
                uint32_t wh[2], wl[2];
                wh[0] = *(const uint32_t*)(sWh + orow * 136 + kw);
                wh[1] = *(const uint32_t*)(sWh + orow * 136 + kw + 8);
                wl[0] = *(const uint32_t*)(sWl + orow * 136 + kw);
                wl[1] = *(const uint32_t*)(sWl + orow * 136 + kw + 8);
                mma16816(acc[0][nt], ah[0], wh);
                mma16816(acc[0][nt], al[0], wh);
                mma16816(acc[0][nt], ah[0], wl);
                mma16816(acc[1][nt], ah[1], wh);
                mma16816(acc[1][nt], al[1], wh);
                mma16816(acc[1][nt], ah[1], wl);
            }
        }
        __syncthreads();
    }

    // ---- epilogue: bias, per-pixel L2 norm, staged coalesced stores ----
    #pragma unroll
    for (int nt = 0; nt < 8; nt++) {
        int ob2 = warp_n * 64 + nt * 8 + 2 * tig;
        float bi0 = biasS[ob2], bi1 = biasS[ob2 + 1];
        #pragma unroll
        for (int mt = 0; mt < 2; mt++) {
            acc[mt][nt][0] += bi0; acc[mt][nt][1] += bi1;
            acc[mt][nt][2] += bi0; acc[mt][nt][3] += bi1;
        }
    }

    float s0[2] = {0.f, 0.f}, s1[2] = {0.f, 0.f};
    #pragma unroll
    for (int mt = 0; mt < 2; mt++)
        #pragma unroll
        for (int nt = 0; nt < 8; nt++) {
            s0[mt] += acc[mt][nt][0] * acc[mt][nt][0] + acc[mt][nt][1] * acc[mt][nt][1];
            s1[mt] += acc[mt][nt][2] * acc[mt][nt][2] + acc[mt][nt][3] * acc[mt][nt][3];
        }
    #pragma unroll
    for (int off = 1; off <= 2; off <<= 1) {
        s0[0] += __shfl_xor_sync(0xFFFFFFFF, s0[0], off);
        s0[1] += __shfl_xor_sync(0xFFFFFFFF, s0[1], off);
        s1[0] += __shfl_xor_sync(0xFFFFFFFF, s1[0], off);
        s1[1] += __shfl_xor_sync(0xFFFFFFFF, s1[1], off);
    }
    if (tig == 0) {
        #pragma unroll
        for (int mt = 0; mt < 2; mt++) {
            int px = warp_m * 32 + mt * 16 + gid;
            atomicAdd(&ssS[px], s0[mt]);
            atomicAdd(&ssS[px + 8], s1[mt]);
        }
    }
    __syncthreads();
    if (t < 128) ssS[t] = 1.f / (sqrtf(ssS[t]) + 1e-8f);
    __syncthreads();

    #pragma unroll
    for (int mt = 0; mt < 2; mt++) {
        int px = warp_m * 32 + mt * 16 + gid;
        float iv0 = ssS[px], iv1 = ssS[px + 8];
        #pragma unroll
        for (int nt = 0; nt < 8; nt++) {
            int o = warp_n * 64 + nt * 8 + 2 * tig;
            outSt[o * 132 + px]            = acc[mt][nt][0] * iv0;
            outSt[(o + 1) * 132 + px]      = acc[mt][nt][1] * iv0;
            outSt[o * 132 + px + 8]        = acc[mt][nt][2] * iv1;
            outSt[(o + 1) * 132 + px + 8]  = acc[mt][nt][3] * iv1;
        }
    }
    __syncthreads();

    #pragma unroll
    for (int it = 0; it < 16; it++) {
        int idx = t + it * 256;                // 4096 float4
        int o = idx >> 5, q = idx & 31;
        float4 v = *(const float4*)&outSt[o * 132 + q * 4];
        *(float4*)&outp[((size_t)b * Ff + o) * HW + rem + q * 4] = v;
    }
}

// ---------------- fused correlation + selector (R5-verbatim) ----------------
__global__ __launch_bounds__(224) void corrsel_kernel(const float* __restrict__ cv0,
                                                      const float* __restrict__ cv1,
                                                      const float* __restrict__ cv2,
                                                      float* __restrict__ out)
{
    float* s1c  = dynsm;
    float* s2c  = dynsm + 4352;
    float* cvS  = s2c + 7424;
    float* wsm  = cvS + 9408;
    float* outS = s1c;
    float* Msm  = s1c + 3136;
    float* betaS= Msm + 441;

    int t   = threadIdx.x;
    int blk = blockIdx.x;
    int bh  = blk >> 2;
    int x0  = (blk & 3) * 64;
    int b   = bh / Hh, h = bh % Hh;

    for (int idx = t; idx < 3 * CVC * 16; idx += 224) {
        int v = idx / (CVC * 16);
        int r = idx - v * (CVC * 16);
        int c = r >> 4, q = r & 15;
        const float* src = (v == 0 ? cv0 : (v == 1 ? cv1 : cv2));
        cp16(&cvS[(v * CVC + c) * 64 + q * 4],
             &src[((size_t)(b * CVC + c) * Hh + h) * Wd + x0 + q * 4]);
    }
    cp_commit();

    const float* f1 = g_f1n + (size_t)b * Ff * HW + (size_t)h * Wd;
    const float* f2 = g_f2n + (size_t)b * Ff * HW + (size_t)h * Wd;

    int xt = t & 15, j = t >> 4;
    bool active = (j < 13);

    unsigned long long acc[4][2];
    #pragma unroll
    for (int i = 0; i < 4; i++) { acc[i][0] = 0ULL; acc[i][1] = 0ULL; }

    for (int half = 0; half < 2; half++) {
        __syncthreads();
        int cbase = half * 64;
        for (int idx = t; idx < 1024; idx += 224) {
            int o = idx >> 4, q = idx & 15;
            *(float4*)&s1c[o * 68 + q * 4] =
                *(const float4*)&f1[(size_t)(cbase + o) * HW + x0 + q * 4];
        }
        for (int idx = t; idx < 1792; idx += 224) {
            int o = idx / 28, q = idx - o * 28;
            int xg = x0 - RAD + q * 4;
            float4 vv = make_float4(0.f, 0.f, 0.f, 0.f);
            if (xg >= 0 && xg <= Wd - 4)
                vv = *(const float4*)&f2[(size_t)(cbase + o) * HW + xg];
            *(float4*)&s2c[o * 116 + q * 4] = vv;
        }
        __syncthreads();

        if (active) {
            #pragma unroll 4
            for (int o = 0; o < 64; o++) {
                float4 a = *(const float4*)&s1c[o * 68 + 4 * xt];
                ulonglong2 bb = *(const ulonglong2*)&s2c[o * 116 + 4 * (xt + j)];
                float av[4] = {a.x, a.y, a.z, a.w};
                #pragma unroll
                for (int i = 0; i < 4; i++) {
                    unsigned long long aa = bcast2(av[i]);
                    ffma2(acc[i][0], aa, bb.x);
                    ffma2(acc[i][1], aa, bb.y);
                }
            }
        }
    }

    __syncthreads();

    if (active) {
        #pragma unroll
        for (int i = 0; i < 4; i++) {
            float vals[4];
            unpack2(acc[i][0], vals[0], vals[1]);
            unpack2(acc[i][1], vals[2], vals[3]);
            #pragma unroll
            for (int ip = 0; ip < 4; ip++) {
                int k = 48 - 4 * j + i - ip;
                if (k >= 0 && k <= 48)
                    outS[k * 64 + 4 * xt + i] = vals[ip];
            }
        }
    }
    for (int i = t; i < 9 * CVC; i += 224) Msm[i] = g_M[i];
    if (t < 3) betaS[t] = g_beta[t];
    cp_wait<0>();
    __syncthreads();

    if (t < 192) {
        int j2 = t >> 6;
        int x  = t & 63;
        float l = betaS[j2];
        const float* M0 = Msm + 0 * 3 * CVC + j2 * CVC;
        const float* M1 = Msm + 1 * 3 * CVC + j2 * CVC;
        const float* M2 = Msm + 2 * 3 * CVC + j2 * CVC;
        #pragma unroll 7
        for (int c = 0; c < CVC; c++) {
            l = fmaf(M0[c], cvS[(0 * CVC + c) * 64 + x],
                fmaf(M1[c], cvS[(1 * CVC + c) * 64 + x],
                fmaf(M2[c], cvS[(2 * CVC + c) * 64 + x], l)));
        }
        wsm[j2 * 64 + x] = l;
    }
    __syncthreads();

    if (t < 64) {
        float l0 = wsm[t], l1 = wsm[64 + t], l2 = wsm[128 + t];
        float m  = fmaxf(l0, fmaxf(l1, l2));
        float e0 = expf(l0 - m), e1 = expf(l1 - m), e2 = expf(l2 - m);
        float inv = 1.f / (e0 + e1 + e2);
        float w0 = e0 * inv, w1 = e1 * inv, w2 = e2 * inv;
        wsm[t] = w0; wsm[64 + t] = w1; wsm[128 + t] = w2;
        float* wout = out + 2 * NC_ + ((size_t)b * 3 * Hh + h) * Wd + x0 + t;
        wout[0]              = w0;
        wout[(size_t)HW]     = w1;
        wout[(size_t)2 * HW] = w2;
    }
    __syncthreads();

    for (int idx = t; idx < CVC * 16; idx += 224) {
        int k = idx >> 4, q = idx & 15;
        float4 corr4 = *(const float4*)&outS[k * 64 + q * 4];
        float4 a0 = *(const float4*)&cvS[(0 * CVC + k) * 64 + q * 4];
        float4 a1 = *(const float4*)&cvS[(1 * CVC + k) * 64 + q * 4];
        float4 a2 = *(const float4*)&cvS[(2 * CVC + k) * 64 + q * 4];
        float4 w0 = *(const float4*)&wsm[0 * 64 + q * 4];
        float4 w1 = *(const float4*)&wsm[1 * 64 + q * 4];
        float4 w2 = *(const float4*)&wsm[2 * 64 + q * 4];
        float4 fin;
        fin.x = corr4.x + fmaf(w0.x, a0.x, fmaf(w1.x, a1.x, w2.x * a2.x));
        fin.y = corr4.y + fmaf(w0.y, a0.y, fmaf(w1.y, a1.y, w2.y * a2.y));
        fin.z = corr4.z + fmaf(w0.z, a0.z, fmaf(w1.z, a1.z, w2.z * a2.z));
        fin.w = corr4.w + fmaf(w0.w, a0.w, fmaf(w1.w, a1.w, w2.w * a2.w));
        size_t off = ((size_t)(b * CVC + k) * Hh + h) * Wd + x0 + q * 4;
        *(float4*)&out[off]       = fin;
        *(float4*)&out[NC_ + off] = corr4;
    }
}

// ---------------- launch ----------------
extern "C" void kernel_launch(void* const* d_in, const int* in_sizes, int n_in,
                              void* d_out, int out_size)
{
    const float* feat_l1 = (const float*)d_in[0];
    const float* feat_r1 = (const float*)d_in[1];
    const float* cv0     = (const float*)d_in[2];
    const float* cv1     = (const float*)d_in[3];
    const float* cv2     = (const float*)d_in[4];
    const float* W_f1    = (const float*)d_in[5];
    const float* b_f1    = (const float*)d_in[6];
    const float* W_f2    = (const float*)d_in[7];
    const float* b_f2    = (const float*)d_in[8];
    const float* W_geo   = (const float*)d_in[9];
    const float* b_geo   = (const float*)d_in[10];
    const float* W_sel   = (const float*)d_in[11];
    const float* b_sel   = (const float*)d_in[12];
    float* out = (float*)d_out;

    static int fm_set = 0;
    if (!fm_set) {
        cudaFuncSetAttribute(fmap_kernel, cudaFuncAttributeMaxDynamicSharedMemorySize, FM_SMEM_BYTES);
        fm_set = 1;
    }
    fmap_kernel<<<dim3(NPIX / 128, 2), 256, FM_SMEM_BYTES>>>(feat_l1, feat_r1,
                                                             W_f1, W_f2, b_f1, b_f2);

    prep_kernel<<<4, 256>>>(W_geo, b_geo, W_sel, b_sel);

    int cs_smem = (4352 + 7424 + 9408 + 192) * (int)sizeof(float);            // ~85.5KB
    static int cs_set = 0;
    if (!cs_set) {
        cudaFuncSetAttribute(corrsel_kernel, cudaFuncAttributeMaxDynamicSharedMemorySize, cs_smem);
        cs_set = 1;
    }
    corrsel_kernel<<<Bn * Hh * (Wd / 64), 224, cs_smem>>>(cv0, cv1, cv2, out);
}

// round 12
// speedup vs baseline: 2.3278x; 1.5393x over previous
#include <cuda_runtime.h>
#include <cuda_bf16.h>
#include <cstdint>
#include <cstddef>

// ---------------- problem constants ----------------
#define Bn   4
#define Cc   128
#define Hh   128
#define Wd   256
#define HW   (Hh*Wd)          // 32768
#define Ff   128
#define CVC  49
#define RAD  24
#define NPIX (Bn*HW)          // 131072
static const size_t NC_ = (size_t)Bn * CVC * HW;  // elements per corr-like tensor

// ---------------- device scratch (static, no allocation) ----------------
__device__ float g_f1n[(size_t)NPIX * Ff];   // [B][F][H][W]
__device__ float g_f2n[(size_t)NPIX * Ff];
__device__ float g_M[9 * CVC];               // [i][j][c], i=volume, j=logit
__device__ float g_beta[3];
// pre-split W images, padded row stride 136 halfwords (matches smem layout)
__device__ uint16_t g_W1h[Ff * 136];
__device__ uint16_t g_W1l[Ff * 136];
__device__ uint16_t g_W2h[Ff * 136];
__device__ uint16_t g_W2l[Ff * 136];

// ---------------- helpers ----------------
__device__ __forceinline__ unsigned long long bcast2(float v) {
    unsigned long long r; asm("mov.b64 %0, {%1,%1};" : "=l"(r) : "f"(v)); return r;
}
__device__ __forceinline__ void unpack2(unsigned long long p, float& lo, float& hi) {
    asm("mov.b64 {%0,%1}, %2;" : "=f"(lo), "=f"(hi) : "l"(p));
}
__device__ __forceinline__ void ffma2(unsigned long long& acc, unsigned long long a, unsigned long long b) {
    asm("fma.rn.f32x2 %0, %1, %2, %0;" : "+l"(acc) : "l"(a), "l"(b));
}
__device__ __forceinline__ void cp16(void* smem_dst, const void* gmem_src) {
    unsigned int s = (unsigned int)__cvta_generic_to_shared(smem_dst);
    asm volatile("cp.async.cg.shared.global [%0], [%1], 16;" :: "r"(s), "l"(gmem_src));
}
__device__ __forceinline__ void cp_commit() { asm volatile("cp.async.commit_group;"); }
template <int N>
__device__ __forceinline__ void cp_wait() { asm volatile("cp.async.wait_group %0;" :: "n"(N)); }

// bf16 warp MMA m16n8k16, A row-major, B col-major, fp32 accum.
__device__ __forceinline__ void mma16816(float* d, const uint32_t* a, const uint32_t* b) {
    asm volatile("mma.sync.aligned.m16n8k16.row.col.f32.bf16.bf16.f32 "
                 "{%0,%1,%2,%3}, {%4,%5,%6,%7}, {%8,%9}, {%0,%1,%2,%3};"
                 : "+f"(d[0]), "+f"(d[1]), "+f"(d[2]), "+f"(d[3])
                 : "r"(a[0]), "r"(a[1]), "r"(a[2]), "r"(a[3]), "r"(b[0]), "r"(b[1]));
}

// split two fp32 into packed-bf16x2 hi and lo words (low half = first element)
__device__ __forceinline__ void split2(float a, float b, uint32_t& h, uint32_t& l) {
    __nv_bfloat16 ha = __float2bfloat16(a), hb = __float2bfloat16(b);
    float ra = a - __bfloat162float(ha), rb = b - __bfloat162float(hb);
    __nv_bfloat16 la = __float2bfloat16(ra), lb = __float2bfloat16(rb);
    h = (uint32_t)*(uint16_t*)&ha | ((uint32_t)*(uint16_t*)&hb << 16);
    l = (uint32_t)*(uint16_t*)&la | ((uint32_t)*(uint16_t*)&lb << 16);
}

// ---------------- prep: selector fold + W split images ----------------
// blocks 0..2: M per volume; 3: beta; 4..11: W hi/lo split (padded stride 136).
__global__ void prep_kernel(const float* __restrict__ Wgeo, const float* __restrict__ bgeo,
                            const float* __restrict__ Wsel, const float* __restrict__ bsel,
                            const float* __restrict__ WfA,  const float* __restrict__ WfB)
{
    int blk = blockIdx.x, t = threadIdx.x;
    if (blk < 3) {
        int i = blk;                                 // volume index
        for (int r = t; r < 3 * CVC; r += 256) {     // j*CVC + c
            int j = r / CVC, c = r % CVC;
            float s = 0.f;
            #pragma unroll 8
            for (int m = 0; m < 96; m++)
                s += Wsel[j * 288 + i * 96 + m] * Wgeo[m * CVC + c];
            g_M[i * 3 * CVC + j * CVC + c] = s;
        }
    } else if (blk == 3) {
        if (t < 3) {
            float s = bsel[t];
            for (int q = 0; q < 288; q++)
                s += Wsel[t * 288 + q] * bgeo[q % 96];
            g_beta[t] = s;
        }
    } else {
        int blk4 = blk - 4;                     // 0..7
        int mat  = blk4 >> 2;                   // 0 -> W1, 1 -> W2
        int part = blk4 & 3;                    // quarter of 16384 elems
        const float* src = mat ? WfB : WfA;
        uint16_t* dh = mat ? g_W2h : g_W1h;
        uint16_t* dl = mat ? g_W2l : g_W1l;
        #pragma unroll
        for (int it = 0; it < 16; it++) {
            int idx = part * 4096 + it * 256 + t;   // [o][c]
            int o = idx >> 7, c = idx & 127;
            float v = src[idx];
            __nv_bfloat16 h = __float2bfloat16(v);
            float rv = v - __bfloat162float(h);
            __nv_bfloat16 l = __float2bfloat16(rv);
            dh[o * 136 + c] = *(uint16_t*)&h;
            dl[o * 136 + c] = *(uint16_t*)&l;
        }
    }
}

// ---------------- fmap via HMMA, K-pipelined, pre-split W ----------------
#define WH_OFF   0            // uint16[128][136]  34816 B
#define WL_OFF   34816        // uint16[128][136]  34816 B
#define A_OFF    69632        // fp32 [2][32][132] 2x16896 B
#define BIAS_OFF 103424       // fp32[128]
#define SS_OFF   103936       // fp32[128]
#define FM_SMEM_BYTES 104448

extern __shared__ float dynsm[];

__global__ __launch_bounds__(256, 2) void fmap_kernel(
    const float* __restrict__ featA, const float* __restrict__ featB,
    const float* __restrict__ biasA, const float* __restrict__ biasB)
{
    char* smc = (char*)dynsm;
    uint16_t* sWh = (uint16_t*)(smc + WH_OFF);
    uint16_t* sWl = (uint16_t*)(smc + WL_OFF);
    float* sA0   = (float*)(smc + A_OFF);
    float* sA1   = sA0 + 32 * 132;
    float* biasS = (float*)(smc + BIAS_OFF);
    float* ssS   = (float*)(smc + SS_OFF);
    float* outSt = (float*)smc;               // reuses W region post-compute
    float* stg[2] = {sA0, sA1};

    int which = blockIdx.y;
    const float* feat = which ? featB : featA;
    const float* bias = which ? biasB : biasA;
    const uint16_t* gWh = which ? g_W2h : g_W1h;
    const uint16_t* gWl = which ? g_W2l : g_W1l;
    float* outp = which ? g_f2n : g_f1n;

    int t    = threadIdx.x;
    int wid  = t >> 5, lane = t & 31;
    int gid  = lane >> 2, tig = lane & 3;
    int warp_m = wid & 3, warp_n = wid >> 2;
    int p0  = blockIdx.x * 128;
    int b   = p0 / HW;
    int rem = p0 % HW;
    const float* fbase = feat + (size_t)b * Cc * HW + rem;

    if (t < 128) { biasS[t] = bias[t]; ssS[t] = 0.f; }

    // A chunk 0 prefetch
    #pragma unroll
    for (int it = 0; it < 4; it++) {
        int idx = t + it * 256;
        int c = idx >> 5, q = idx & 31;
        cp16(&sA0[c * 132 + q * 4], &fbase[(size_t)c * HW + q * 4]);
    }
    cp_commit();

    // W hi/lo: linear 16B copies of pre-split images (4352 cp16 / 256 = 17 each)
    #pragma unroll
    for (int it = 0; it < 17; it++) {
        int idx = t + it * 256;                // 0..4351
        int half = idx >= 2176;
        int i = idx - half * 2176;
        int row = i / 17, seg = i % 17;
        if (half) cp16(sWl + row * 136 + seg * 8, gWl + row * 136 + seg * 8);
        else      cp16(sWh + row * 136 + seg * 8, gWh + row * 136 + seg * 8);
    }
    cp_commit();

    float acc[2][8][4];
    #pragma unroll
    for (int mt = 0; mt < 2; mt++)
        #pragma unroll
        for (int nt = 0; nt < 8; nt++)
            #pragma unroll
            for (int r = 0; r < 4; r++) acc[mt][nt][r] = 0.f;

    int row0 = warp_m * 32 + gid;

    #pragma unroll
    for (int ch = 0; ch < 4; ch++) {
        if (ch < 3) {
            float* dst = stg[(ch + 1) & 1];
            const float* src = fbase + (size_t)(ch + 1) * 32 * HW;
            #pragma unroll
            for (int it = 0; it < 4; it++) {
                int idx = t + it * 256;
                int c = idx >> 5, q = idx & 31;
                cp16(&dst[c * 132 + q * 4], &src[(size_t)c * HW + q * 4]);
            }
            cp_commit();
            cp_wait<1>();
        } else {
            cp_wait<0>();
        }
        __syncthreads();

        const float* A = stg[ch & 1];
        #pragma unroll
        for (int ks = 0; ks < 2; ks++) {
            int kb = ks * 16 + 2 * tig;
            uint32_t ah[2][4], al[2][4];
            #pragma unroll
            for (int mt = 0; mt < 2; mt++) {
                int row = row0 + mt * 16;
                float f0 = A[kb * 132 + row],        f1 = A[(kb + 1) * 132 + row];
                float f2 = A[kb * 132 + row + 8],    f3 = A[(kb + 1) * 132 + row + 8];
                float f4 = A[(kb + 8) * 132 + row],  f5 = A[(kb + 9) * 132 + row];
                float f6 = A[(kb + 8) * 132 + row + 8], f7 = A[(kb + 9) * 132 + row + 8];
                split2(f0, f1, ah[mt][0], al[mt][0]);
                split2(f2, f3, ah[mt][1], al[mt][1]);
                split2(f4, f5, ah[mt][2], al[mt][2]);
                split2(f6, f7, ah[mt][3], al[mt][3]);
            }
            int kw = ch * 32 + kb;
            #pragma unroll
            for (int nt = 0; nt < 8; nt++) {
                int orow = warp_n * 64 + nt * 8 + gid;
                uint32_t wh[2], wl[2];
                wh[0] = *(const uint32_t*)(sWh + orow * 136 + kw);
                wh[1] = *(const uint32_t*)(sWh + orow * 136 + kw + 8);
                wl[0] = *(const uint32_t*)(sWl + orow * 136 + kw);
                wl[1] = *(const uint32_t*)(sWl + orow * 136 + kw + 8);
                mma16816(acc[0][nt], ah[0], wh);
                mma16816(acc[0][nt], al[0], wh);
                mma16816(acc[0][nt], ah[0], wl);
                mma16816(acc[1][nt], ah[1], wh);
                mma16816(acc[1][nt], al[1], wh);
                mma16816(acc[1][nt], ah[1], wl);
            }
        }
        __syncthreads();
    }

    // ---- epilogue: bias, per-pixel L2 norm, staged coalesced stores ----
    #pragma unroll
    for (int nt = 0; nt < 8; nt++) {
        int ob2 = warp_n * 64 + nt * 8 + 2 * tig;
        float bi0 = biasS[ob2], bi1 = biasS[ob2 + 1];
        #pragma unroll
        for (int mt = 0; mt < 2; mt++) {
            acc[mt][nt][0] += bi0; acc[mt][nt][1] += bi1;
            acc[mt][nt][2] += bi0; acc[mt][nt][3] += bi1;
        }
    }

    float s0[2] = {0.f, 0.f}, s1[2] = {0.f, 0.f};
    #pragma unroll
    for (int mt = 0; mt < 2; mt++)
        #pragma unroll
        for (int nt = 0; nt < 8; nt++) {
            s0[mt] += acc[mt][nt][0] * acc[mt][nt][0] + acc[mt][nt][1] * acc[mt][nt][1];
            s1[mt] += acc[mt][nt][2] * acc[mt][nt][2] + acc[mt][nt][3] * acc[mt][nt][3];
        }
    #pragma unroll
    for (int off = 1; off <= 2; off <<= 1) {
        s0[0] += __shfl_xor_sync(0xFFFFFFFF, s0[0], off);
        s0[1] += __shfl_xor_sync(0xFFFFFFFF, s0[1], off);
        s1[0] += __shfl_xor_sync(0xFFFFFFFF, s1[0], off);
        s1[1] += __shfl_xor_sync(0xFFFFFFFF, s1[1], off);
    }
    if (tig == 0) {
        #pragma unroll
        for (int mt = 0; mt < 2; mt++) {
            int px = warp_m * 32 + mt * 16 + gid;
            atomicAdd(&ssS[px], s0[mt]);
            atomicAdd(&ssS[px + 8], s1[mt]);
        }
    }
    __syncthreads();
    if (t < 128) ssS[t] = 1.f / (sqrtf(ssS[t]) + 1e-8f);
    __syncthreads();

    #pragma unroll
    for (int mt = 0; mt < 2; mt++) {
        int px = warp_m * 32 + mt * 16 + gid;
        float iv0 = ssS[px], iv1 = ssS[px + 8];
        #pragma unroll
        for (int nt = 0; nt < 8; nt++) {
            int o = warp_n * 64 + nt * 8 + 2 * tig;
            outSt[o * 132 + px]            = acc[mt][nt][0] * iv0;
            outSt[(o + 1) * 132 + px]      = acc[mt][nt][1] * iv0;
            outSt[o * 132 + px + 8]        = acc[mt][nt][2] * iv1;
            outSt[(o + 1) * 132 + px + 8]  = acc[mt][nt][3] * iv1;
        }
    }
    __syncthreads();

    #pragma unroll
    for (int it = 0; it < 16; it++) {
        int idx = t + it * 256;
        int o = idx >> 5, q = idx & 31;
        float4 v = *(const float4*)&outSt[o * 132 + q * 4];
        *(float4*)&outp[((size_t)b * Ff + o) * HW + rem + q * 4] = v;
    }
}

// ---------------- fused correlation + selector, 4-quarter cp.async pipeline ----------------
// smem (floats): stage0 {s1 2176, s2 3712} @0, stage1 @5888, cvS @11776 (9408),
// wsm @21184 (192), Msm @21376 (441), beta @21817. outS reuses [0..3136).
#define CS_STG 5888
#define CS_SMEM_BYTES (21820 * 4)

__global__ __launch_bounds__(224) void corrsel_kernel(const float* __restrict__ cv0,
                                                      const float* __restrict__ cv1,
                                                      const float* __restrict__ cv2,
                                                      float* __restrict__ out)
{
    float* cvS  = dynsm + 11776;
    float* wsm  = dynsm + 21184;
    float* Msm  = dynsm + 21376;
    float* betaS= dynsm + 21817;
    float* outS = dynsm;

    int t   = threadIdx.x;
    int blk = blockIdx.x;
    int bh  = blk >> 2;
    int x0  = (blk & 3) * 64;
    int b   = bh / Hh, h = bh % Hh;

    // group 1: cv tiles
    for (int idx = t; idx < 3 * CVC * 16; idx += 224) {
        int v = idx / (CVC * 16);
        int r = idx - v * (CVC * 16);
        int c = r >> 4, q = r & 15;
        const float* src = (v == 0 ? cv0 : (v == 1 ? cv1 : cv2));
        cp16(&cvS[(v * CVC + c) * 64 + q * 4],
             &src[((size_t)(b * CVC + c) * Hh + h) * Wd + x0 + q * 4]);
    }
    cp_commit();

    const float* f1 = g_f1n + (size_t)b * Ff * HW + (size_t)h * Wd;
    const float* f2 = g_f2n + (size_t)b * Ff * HW + (size_t)h * Wd;

    auto load_q = [&](int qq, int s) {
        float* s1 = dynsm + s * CS_STG;
        float* s2 = dynsm + s * CS_STG + 2176;
        int cb = qq * 32;
        for (int idx = t; idx < 512; idx += 224) {         // 32 ch x 16 float4
            int o = idx >> 4, q = idx & 15;
            cp16(&s1[o * 68 + q * 4], &f1[(size_t)(cb + o) * HW + x0 + q * 4]);
        }
        for (int idx = t; idx < 896; idx += 224) {         // 32 ch x 28 float4
            int o = idx / 28, q = idx - o * 28;
            int xg = x0 - RAD + q * 4;
            if (xg >= 0 && xg <= Wd - 4)
                cp16(&s2[o * 116 + q * 4], &f2[(size_t)(cb + o) * HW + xg]);
            else
                *(float4*)&s2[o * 116 + q * 4] = make_float4(0.f, 0.f, 0.f, 0.f);
        }
        cp_commit();
    };

    load_q(0, 0);                                          // group 2

    int xt = t & 15, j = t >> 4;       // j 0..13 (j==13 -> load-only helper)
    bool active = (j < 13);

    unsigned long long acc[4][2];
    #pragma unroll
    for (int i = 0; i < 4; i++) { acc[i][0] = 0ULL; acc[i][1] = 0ULL; }

    #pragma unroll
    for (int qq = 0; qq < 4; qq++) {
        if (qq < 3) { load_q(qq + 1, (qq + 1) & 1); cp_wait<1>(); }
        else        { cp_wait<0>(); }
        __syncthreads();

        if (active) {
            const float* s1c = dynsm + (qq & 1) * CS_STG;
            const float* s2c = s1c + 2176;
            #pragma unroll 4
            for (int o = 0; o < 32; o++) {
                float4 a = *(const float4*)&s1c[o * 68 + 4 * xt];
                ulonglong2 bb = *(const ulonglong2*)&s2c[o * 116 + 4 * (xt + j)];
                float av[4] = {a.x, a.y, a.z, a.w};
                #pragma unroll
                for (int i = 0; i < 4; i++) {
                    unsigned long long aa = bcast2(av[i]);
                    ffma2(acc[i][0], aa, bb.x);
                    ffma2(acc[i][1], aa, bb.y);
                }
            }
        }
        __syncthreads();
    }

    // ---- stage corr tile into outS; load M/beta ----
    if (active) {
        #pragma unroll
        for (int i = 0; i < 4; i++) {
            float vals[4];
            unpack2(acc[i][0], vals[0], vals[1]);
            unpack2(acc[i][1], vals[2], vals[3]);
            #pragma unroll
            for (int ip = 0; ip < 4; ip++) {
                int k = 48 - 4 * j + i - ip;
                if (k >= 0 && k <= 48)
                    outS[k * 64 + 4 * xt + i] = vals[ip];
            }
        }
    }
    for (int i = t; i < 9 * CVC; i += 224) Msm[i] = g_M[i];
    if (t < 3) betaS[t] = g_beta[t];
    __syncthreads();

    // ---- folded logits (192 threads: 3 logits x 64 px) ----
    if (t < 192) {
        int j2 = t >> 6;
        int x  = t & 63;
        float l = betaS[j2];
        const float* M0 = Msm + 0 * 3 * CVC + j2 * CVC;
        const float* M1 = Msm + 1 * 3 * CVC + j2 * CVC;
        const float* M2 = Msm + 2 * 3 * CVC + j2 * CVC;
        #pragma unroll 7
        for (int c = 0; c < CVC; c++) {
            l = fmaf(M0[c], cvS[(0 * CVC + c) * 64 + x],
                fmaf(M1[c], cvS[(1 * CVC + c) * 64 + x],
                fmaf(M2[c], cvS[(2 * CVC + c) * 64 + x], l)));
        }
        wsm[j2 * 64 + x] = l;
    }
    __syncthreads();

    // ---- softmax ----
    if (t < 64) {
        float l0 = wsm[t], l1 = wsm[64 + t], l2 = wsm[128 + t];
        float m  = fmaxf(l0, fmaxf(l1, l2));
        float e0 = expf(l0 - m), e1 = expf(l1 - m), e2 = expf(l2 - m);
        float inv = 1.f / (e0 + e1 + e2);
        float w0 = e0 * inv, w1 = e1 * inv, w2 = e2 * inv;
        wsm[t] = w0; wsm[64 + t] = w1; wsm[128 + t] = w2;
        float* wout = out + 2 * NC_ + ((size_t)b * 3 * Hh + h) * Wd + x0 + t;
        wout[0]              = w0;
        wout[(size_t)HW]     = w1;
        wout[(size_t)2 * HW] = w2;
    }
    __syncthreads();

    // ---- final = corr + w·cv ; write final + init_corr ----
    for (int idx = t; idx < CVC * 16; idx += 224) {
        int k = idx >> 4, q = idx & 15;
        float4 corr4 = *(const float4*)&outS[k * 64 + q * 4];
        float4 a0 = *(const float4*)&cvS[(0 * CVC + k) * 64 + q * 4];
        float4 a1 = *(const float4*)&cvS[(1 * CVC + k) * 64 + q * 4];
        float4 a2 = *(const float4*)&cvS[(2 * CVC + k) * 64 + q * 4];
        float4 w0 = *(const float4*)&wsm[0 * 64 + q * 4];
        float4 w1 = *(const float4*)&wsm[1 * 64 + q * 4];
        float4 w2 = *(const float4*)&wsm[2 * 64 + q * 4];
        float4 fin;
        fin.x = corr4.x + fmaf(w0.x, a0.x, fmaf(w1.x, a1.x, w2.x * a2.x));
        fin.y = corr4.y + fmaf(w0.y, a0.y, fmaf(w1.y, a1.y, w2.y * a2.y));
        fin.z = corr4.z + fmaf(w0.z, a0.z, fmaf(w1.z, a1.z, w2.z * a2.z));
        fin.w = corr4.w + fmaf(w0.w, a0.w, fmaf(w1.w, a1.w, w2.w * a2.w));
        size_t off = ((size_t)(b * CVC + k) * Hh + h) * Wd + x0 + q * 4;
        *(float4*)&out[off]       = fin;
        *(float4*)&out[NC_ + off] = corr4;
    }
}

// ---------------- launch ----------------
extern "C" void kernel_launch(void* const* d_in, const int* in_sizes, int n_in,
                              void* d_out, int out_size)
{
    const float* feat_l1 = (const float*)d_in[0];
    const float* feat_r1 = (const float*)d_in[1];
    const float* cv0     = (const float*)d_in[2];
    const float* cv1     = (const float*)d_in[3];
    const float* cv2     = (const float*)d_in[4];
    const float* W_f1    = (const float*)d_in[5];
    const float* b_f1    = (const float*)d_in[6];
    const float* W_f2    = (const float*)d_in[7];
    const float* b_f2    = (const float*)d_in[8];
    const float* W_geo   = (const float*)d_in[9];
    const float* b_geo   = (const float*)d_in[10];
    const float* W_sel   = (const float*)d_in[11];
    const float* b_sel   = (const float*)d_in[12];
    float* out = (float*)d_out;

    prep_kernel<<<12, 256>>>(W_geo, b_geo, W_sel, b_sel, W_f1, W_f2);

    static int fm_set = 0;
    if (!fm_set) {
        cudaFuncSetAttribute(fmap_kernel, cudaFuncAttributeMaxDynamicSharedMemorySize, FM_SMEM_BYTES);
        fm_set = 1;
    }
    fmap_kernel<<<dim3(NPIX / 128, 2), 256, FM_SMEM_BYTES>>>(feat_l1, feat_r1, b_f1, b_f2);

    static int cs_set = 0;
    if (!cs_set) {
        cudaFuncSetAttribute(corrsel_kernel, cudaFuncAttributeMaxDynamicSharedMemorySize, CS_SMEM_BYTES);
        cs_set = 1;
    }
    corrsel_kernel<<<Bn * Hh * (Wd / 64), 224, CS_SMEM_BYTES>>>(cv0, cv1, cv2, out);
}